// round 11
// baseline (speedup 1.0000x reference)
#include <cuda_runtime.h>
#include <cstdint>

// LoRA linear via rank-16 factor:
//   t   = x @ A^T   : [16384,4096] @ [4096,16] -> [16384,16]   (stage 1, R6 fp32)
//   out = t @ B^T   : [16384,16]   @ [16,4096] -> [16384,4096] (stage 2, lane-per-row)

#define D 4096
#define R 16
#define ROWS_TOTAL 16384
#define KC 32
#define NCH (D / KC)        // 128 chunks
#define ADS 18              // ad row stride in u64
#define AD_STAGE (16 * ADS)

typedef unsigned long long u64;

__device__ float g_t[ROWS_TOTAL * R];   // 1 MB scratch (fully overwritten)

__device__ __forceinline__ u64 fma2(u64 a, u64 b, u64 c) {
    u64 d; asm("fma.rn.f32x2 %0,%1,%2,%3;" : "=l"(d) : "l"(a), "l"(b), "l"(c)); return d;
}
__device__ __forceinline__ u64 pack2(float lo, float hi) {
    u64 d; asm("mov.b64 %0,{%1,%2};" : "=l"(d) : "f"(lo), "f"(hi)); return d;
}
__device__ __forceinline__ float hsum2(u64 v) {
    float lo, hi; asm("mov.b64 {%0,%1},%2;" : "=f"(lo), "=f"(hi) : "l"(v)); return lo + hi;
}
__device__ __forceinline__ void cp16(uint32_t d, const void* s) {
    asm volatile("cp.async.cg.shared.global [%0],[%1],16;" :: "r"(d), "l"(s));
}
__device__ __forceinline__ void cpcommit() { asm volatile("cp.async.commit_group;"); }
__device__ __forceinline__ void cpwait2()  { asm volatile("cp.async.wait_group 2;"); }

// ---------------- Stage 1: t = x @ A^T ---------------- (R6 exact, ~84us)
__global__ void __launch_bounds__(256, 2)
lora_stage1(const float* __restrict__ x, const float* __restrict__ A)
{
    __shared__ __align__(16) unsigned char sm[42 * 1024];
    float* xs = (float*)sm;                  // [4][64 rows][32 k]  32 KB
    u64*   ad = (u64*)(sm + 32768);          // [4][16][ADS]        9.2 KB
    float* redf = (float*)sm;                // [8][64*17] overlay

    const int tid  = threadIdx.x;
    const int w    = tid >> 5;
    const int lane = tid & 31;
    const long rowBase = (long)blockIdx.x * 64;

    const int trow = tid >> 2, tseg = tid & 3;
    const int tsw  = (trow >> 1) & 7;
    const int tph0 = (2 * tseg)     ^ tsw;
    const int tph1 = (2 * tseg + 1) ^ tsw;
    const float* xsrc = x + (rowBase + trow) * D;
    const uint32_t xs_sh = (uint32_t)__cvta_generic_to_shared(sm);

    const int ar = tid >> 4, akp = tid & 15;
    const float* asrc = A + (long)ar * D + 2 * akp;

    const int r0  = 2 * lane;
    const int pcs = (w ^ (lane & 7)) * 4;

    u64 acc0[16], acc1[16];
    #pragma unroll
    for (int r = 0; r < 16; ++r) { acc0[r] = 0ULL; acc1[r] = 0ULL; }

    #pragma unroll
    for (int cc = 0; cc < 3; ++cc) {
        const float* xp = xsrc + cc * KC + tseg * 8;
        cp16(xs_sh + (uint32_t)(cc * 2048 + trow * 32 + tph0 * 4) * 4u, xp);
        cp16(xs_sh + (uint32_t)(cc * 2048 + trow * 32 + tph1 * 4) * 4u, xp + 4);
        cpcommit();
    }
    {
        float2 t0 = *(const float2*)(asrc);
        float2 t1 = *(const float2*)(asrc + KC);
        ad[0 * AD_STAGE + akp * ADS + ar] = pack2(t0.x, t0.y);
        ad[1 * AD_STAGE + akp * ADS + ar] = pack2(t1.x, t1.y);
    }
    float2 apf = *(const float2*)(asrc + 2 * KC);

    #pragma unroll 4
    for (int c = 0; c < NCH; ++c) {
        const int s = c & 3;
        cpwait2();
        __syncthreads();

        if (c + 3 < NCH) {
            const float* xp = xsrc + (c + 3) * KC + tseg * 8;
            const uint32_t base = (uint32_t)(((c + 3) & 3) * 2048 + trow * 32);
            cp16(xs_sh + (base + tph0 * 4) * 4u, xp);
            cp16(xs_sh + (base + tph1 * 4) * 4u, xp + 4);
        }
        cpcommit();

        if (c + 2 < NCH)
            ad[((c + 2) & 3) * AD_STAGE + akp * ADS + ar] = pack2(apf.x, apf.y);
        if (c + 3 < NCH)
            apf = *(const float2*)(asrc + (c + 3) * KC);

        const float* xb = xs + s * 2048;
        ulonglong2 xa = *(const ulonglong2*)(xb + r0 * 32 + pcs);
        ulonglong2 ya = *(const ulonglong2*)(xb + (r0 + 1) * 32 + pcs);
        #pragma unroll
        for (int kp2 = 0; kp2 < 2; ++kp2) {
            const u64 xv = kp2 ? xa.y : xa.x;
            const u64 yv = kp2 ? ya.y : ya.x;
            const u64* adk = ad + s * AD_STAGE + (w * 2 + kp2) * ADS;
            #pragma unroll
            for (int rr = 0; rr < 8; ++rr) {
                ulonglong2 av = *(const ulonglong2*)(adk + 2 * rr);
                acc0[2 * rr]     = fma2(xv, av.x, acc0[2 * rr]);
                acc0[2 * rr + 1] = fma2(xv, av.y, acc0[2 * rr + 1]);
                acc1[2 * rr]     = fma2(yv, av.x, acc1[2 * rr]);
                acc1[2 * rr + 1] = fma2(yv, av.y, acc1[2 * rr + 1]);
            }
        }
    }

    __syncthreads();
    #pragma unroll
    for (int r = 0; r < 16; ++r) {
        redf[w * 1088 + (r0)     * 17 + r] = hsum2(acc0[r]);
        redf[w * 1088 + (r0 + 1) * 17 + r] = hsum2(acc1[r]);
    }
    __syncthreads();

    #pragma unroll
    for (int i = 0; i < 4; ++i) {
        const int e = tid + 256 * i;
        const int row = e >> 4, r = e & 15;
        float s = 0.f;
        #pragma unroll
        for (int ww = 0; ww < 8; ++ww)
            s += redf[ww * 1088 + row * 17 + r];
        g_t[(rowBase + row) * R + r] = s;
    }
}

// ---------------- Stage 2: out = t @ B^T (lane-per-row) ----------------
// Block 256 thr / 8 warps, tile 256 rows x 128 cols, grid (32, 64), 3 CTAs/SM.
// Lane owns row w*32+lane; its t[16] lives in regs (8 f32x2 r-pairs).
// B tile [128 cols][16] in smem; per-column reads are warp-uniform broadcasts.
// Column results buffered in ores[32], transposed through a per-warp 32x33
// smem tile (conflict-free), stored with coalesced STG.128.
__global__ void __launch_bounds__(256, 3)
lora_stage2(const float* __restrict__ B, float* __restrict__ out)
{
    __shared__ u64 bs[128 * 8];            // 8 KB: B[col][r-pair]
    __shared__ float tr[8 * 32 * 33];      // 33.8 KB: per-warp transpose tiles

    const int tid  = threadIdx.x;
    const int w    = tid >> 5;
    const int lane = tid & 31;
    const long rowBase = (long)blockIdx.y * 256;
    const int colBase  = blockIdx.x * 128;

    // load B tile: 2048 floats = 1024 u64, 4 per thread (coalesced)
    {
        const u64* bsrc = (const u64*)(B + (long)colBase * R);
        #pragma unroll
        for (int j = 0; j < 4; ++j)
            bs[tid + 256 * j] = bsrc[tid + 256 * j];
    }
    // load this lane's t row (r-pairs) from g_t
    u64 t[8];
    {
        const u64* tp = (const u64*)(g_t + (rowBase + w * 32 + lane) * R);
        #pragma unroll
        for (int p = 0; p < 8; ++p) t[p] = tp[p];
    }
    __syncthreads();

    float* trw = tr + w * (32 * 33);
    const long orow = (rowBase + w * 32) * (long)D + colBase;

    #pragma unroll
    for (int cg = 0; cg < 4; ++cg) {
        float ores[32];
        const u64* bcol = bs + cg * 32 * 8;
        #pragma unroll
        for (int cc = 0; cc < 32; cc += 2) {
            const u64* b0 = bcol + cc * 8;
            u64 a0 = 0ULL, a1 = 0ULL;
            #pragma unroll
            for (int p = 0; p < 8; ++p) {
                a0 = fma2(t[p], b0[p],     a0);
                a1 = fma2(t[p], b0[8 + p], a1);
            }
            ores[cc]     = hsum2(a0);
            ores[cc + 1] = hsum2(a1);
        }

        // transpose: trw[lane][c] -> coalesced stores
        #pragma unroll
        for (int c = 0; c < 32; ++c)
            trw[lane * 33 + c] = ores[c];
        __syncwarp();

        #pragma unroll
        for (int j = 0; j < 8; ++j) {
            const int i = j * 4 + (lane >> 3);          // local row in tile
            const int cs = (lane & 7) * 4;              // col within group
            const float* src = trw + i * 33 + cs;
            float4 v = make_float4(src[0], src[1], src[2], src[3]);
            *(float4*)(out + orow + (long)i * D + cg * 32 + cs) = v;
        }
        __syncwarp();   // tile free before next cg overwrites
    }
}

extern "C" void kernel_launch(void* const* d_in, const int* in_sizes, int n_in,
                              void* d_out, int out_size) {
    const float* x = (const float*)d_in[0];   // [16384, 4096]
    const float* A = (const float*)d_in[1];   // [16, 4096]
    const float* B = (const float*)d_in[2];   // [4096, 16]
    float* out = (float*)d_out;               // [16384, 4096]

    lora_stage1<<<ROWS_TOTAL / 64, 256>>>(x, A);
    dim3 g2(D / 128, ROWS_TOTAL / 256);
    lora_stage2<<<g2, 256>>>(B, out);
}